// round 3
// baseline (speedup 1.0000x reference)
#include <cuda_runtime.h>
#include <cstdint>

// out = IFFT( D .* FFT( A .* x ) ) per row, C = 4096, complex as (re,im) float pairs.
// A, D scale re/im independently (elementwise).
//
// 128 threads per row, 2 lanes packed per f32x2 register. ALL packed arithmetic
// is expressed as fma.rn.f32x2 (the only real packed-f32 SASS op, FFMA2):
//   a+b = fma(a, ONE, b);  a-b = fma(b, MONE, a);  a*b = fma(a, b, ZERO)
// with ONE/MONE/ZERO loaded from a device global so ptxas cannot fold them
// back into (split) FADD/FMUL pairs.

typedef unsigned long long ull;

#define REV(c) ((((c) & 3) << 2) | ((c) >> 2))

// runtime-opaque packed constants
__device__ ull G_PKC[4] = {0x3F8000003F800000ULL,   // (1.0f, 1.0f)
                           0xBF800000BF800000ULL,   // (-1.0f, -1.0f)
                           0x0000000000000000ULL,   // (0.0f, 0.0f)
                           0ULL};

struct PK { ull one, mone, zero; };

// ---------------- packed f32x2 primitives ----------------
__device__ __forceinline__ ull pk(float a, float b){
    ull r; asm("mov.b64 %0, {%1, %2};" : "=l"(r) : "f"(a), "f"(b)); return r;
}
__device__ __forceinline__ void unpk(ull v, float& a, float& b){
    asm("mov.b64 {%0, %1}, %2;" : "=f"(a), "=f"(b) : "l"(v));
}
__device__ __forceinline__ float plo(ull v){ float a,b; unpk(v,a,b); return a; }
__device__ __forceinline__ float phi(ull v){ float a,b; unpk(v,a,b); return b; }
__device__ __forceinline__ ull pfma(ull a, ull b, ull c){
    ull r; asm("fma.rn.f32x2 %0, %1, %2, %3;" : "=l"(r) : "l"(a), "l"(b), "l"(c)); return r;
}
__device__ __forceinline__ ull padd(ull a, ull b, const PK& q){ return pfma(a, q.one,  b); }
__device__ __forceinline__ ull psub(ull a, ull b, const PK& q){ return pfma(b, q.mone, a); }
__device__ __forceinline__ ull pmul(ull a, ull b, const PK& q){ return pfma(a, b, q.zero); }
__device__ __forceinline__ ull pneg(ull a){   // flip both sign bits (ALU pipe)
    ull r; asm("xor.b64 %0, %1, %2;" : "=l"(r) : "l"(a), "l"(0x8000000080000000ULL)); return r;
}
__device__ __forceinline__ ull pklo(ull A, ull B){ return pk(plo(A), plo(B)); }
__device__ __forceinline__ ull pkhi(ull A, ull B){ return pk(phi(A), phi(B)); }

// packed complex multiply: (r,i) *= (wr,wi)   — 4 FFMA2 + 1 XOR
__device__ __forceinline__ void cmulp(ull& r, ull& i, ull wr, ull wi, const PK& q){
    ull t  = pmul(i, wi, q);                 // i*wi
    ull nr = pfma(r, wr, pneg(t));           // r*wr - i*wi
    ull ni = pfma(r, wi, pmul(i, wr, q));    // r*wi + i*wr
    r = nr; i = ni;
}
// multiply by -i (DIR<0) / +i (DIR>0)
template<int DIR> __device__ __forceinline__ void muljp(ull& r, ull& i){
    ull t = r;
    if (DIR < 0){ r = i;       i = pneg(t); }
    else        { r = pneg(i); i = t; }
}
// constant twiddle, forward (cr, ci_f); inverse = conjugate
template<int DIR> __device__ __forceinline__ void cmulc(ull& r, ull& i, float cr, float ci_f, const PK& q){
    const float ci = (DIR < 0) ? ci_f : -ci_f;
    cmulp(r, i, pk(cr, cr), pk(ci, ci), q);
}

#define TC1 0.92387953251128674f
#define TS1 0.38268343236508978f
#define TC2 0.70710678118654752f

// packed radix-4 butterfly (two lanes at once) — 16 FFMA2 (+1 XOR-free via operand order)
template<int DIR>
__device__ __forceinline__ void fft4p(ull& r0, ull& i0, ull& r1, ull& i1,
                                      ull& r2, ull& i2, ull& r3, ull& i3, const PK& q){
    ull t0r = padd(r0, r2, q), t0i = padd(i0, i2, q);
    ull t1r = psub(r0, r2, q), t1i = psub(i0, i2, q);
    ull t2r = padd(r1, r3, q), t2i = padd(i1, i3, q);
    ull t3r, t3i;
    if (DIR < 0){ t3r = psub(i1, i3, q); t3i = psub(r3, r1, q); }
    else        { t3r = psub(i3, i1, q); t3i = psub(r1, r3, q); }
    r0 = padd(t0r, t2r, q); i0 = padd(t0i, t2i, q);
    r2 = psub(t0r, t2r, q); i2 = psub(t0i, t2i, q);
    r1 = padd(t1r, t3r, q); i1 = padd(t1i, t3i, q);
    r3 = psub(t1r, t3r, q); i3 = psub(t1i, t3i, q);
}

// 16-point DFT, natural slots in -> output c at slot REV(c)
template<int DIR>
__device__ __forceinline__ void fft16_nat_p(ull re[16], ull im[16], const PK& q){
    fft4p<DIR>(re[0],im[0], re[4],im[4], re[8], im[8],  re[12],im[12], q);
    fft4p<DIR>(re[1],im[1], re[5],im[5], re[9], im[9],  re[13],im[13], q);
    fft4p<DIR>(re[2],im[2], re[6],im[6], re[10],im[10], re[14],im[14], q);
    fft4p<DIR>(re[3],im[3], re[7],im[7], re[11],im[11], re[15],im[15], q);
    cmulc<DIR>(re[5], im[5],  TC1, -TS1, q);
    cmulc<DIR>(re[9], im[9],  TC2, -TC2, q);
    cmulc<DIR>(re[13],im[13], TS1, -TC1, q);
    cmulc<DIR>(re[6], im[6],  TC2, -TC2, q);
    muljp<DIR>(re[10],im[10]);
    cmulc<DIR>(re[14],im[14],-TC2, -TC2, q);
    cmulc<DIR>(re[7], im[7],  TS1, -TC1, q);
    cmulc<DIR>(re[11],im[11],-TC2, -TC2, q);
    cmulc<DIR>(re[15],im[15],-TC1,  TS1, q);
    fft4p<DIR>(re[0], im[0],  re[1], im[1],  re[2], im[2],  re[3], im[3],  q);
    fft4p<DIR>(re[4], im[4],  re[5], im[5],  re[6], im[6],  re[7], im[7],  q);
    fft4p<DIR>(re[8], im[8],  re[9], im[9],  re[10],im[10], re[11],im[11], q);
    fft4p<DIR>(re[12],im[12], re[13],im[13], re[14],im[14], re[15],im[15], q);
}

// 16-point DFT, input logical a at slot REV(a) -> natural output slots
template<int DIR>
__device__ __forceinline__ void fft16_rev_p(ull re[16], ull im[16], const PK& q){
    fft4p<DIR>(re[0], im[0],  re[1], im[1],  re[2], im[2],  re[3], im[3],  q);
    fft4p<DIR>(re[4], im[4],  re[5], im[5],  re[6], im[6],  re[7], im[7],  q);
    fft4p<DIR>(re[8], im[8],  re[9], im[9],  re[10],im[10], re[11],im[11], q);
    fft4p<DIR>(re[12],im[12], re[13],im[13], re[14],im[14], re[15],im[15], q);
    cmulc<DIR>(re[5], im[5],  TC1, -TS1, q);
    cmulc<DIR>(re[6], im[6],  TC2, -TC2, q);
    cmulc<DIR>(re[7], im[7],  TS1, -TC1, q);
    cmulc<DIR>(re[9], im[9],  TC2, -TC2, q);
    muljp<DIR>(re[10],im[10]);
    cmulc<DIR>(re[11],im[11],-TC2, -TC2, q);
    cmulc<DIR>(re[13],im[13], TS1, -TC1, q);
    cmulc<DIR>(re[14],im[14],-TC2, -TC2, q);
    cmulc<DIR>(re[15],im[15],-TC1,  TS1, q);
    fft4p<DIR>(re[0],im[0], re[4],im[4], re[8], im[8],  re[12],im[12], q);
    fft4p<DIR>(re[1],im[1], re[5],im[5], re[9], im[9],  re[13],im[13], q);
    fft4p<DIR>(re[2],im[2], re[6],im[6], re[10],im[10], re[14],im[14], q);
    fft4p<DIR>(re[3],im[3], re[7],im[7], re[11],im[11], re[15],im[15], q);
}

// apply w^k to v[slot(k)], k=1..15; w = e^{DIR*i*theta_lane} (two lanes)
template<int DIR, int RV>
__device__ __forceinline__ void twiddle_stage_p(ull re[16], ull im[16],
                                                float th0, float th1, const PK& q){
    float s0, c0, s1, c1;
    __sincosf(th0, &s0, &c0);
    __sincosf(th1, &s1, &c1);
    if (DIR < 0){ s0 = -s0; s1 = -s1; }
    ull wr = pk(c0, c1), wi = pk(s0, s1);
    ull w2r = psub(pmul(wr, wr, q), pmul(wi, wi, q), q);
    ull w2i = padd(pmul(wr, wi, q), pmul(wi, wr, q), q);
    ull por = wr,  poi = wi;   // odd powers
    ull per = w2r, pei = w2i;  // even powers
    #pragma unroll
    for (int k = 1; k < 16; ++k){
        const int slot = RV ? REV(k) : k;
        if (k & 1){
            cmulp(re[slot], im[slot], por, poi, q);
            if (k + 2 < 16) cmulp(por, poi, w2r, w2i, q);
        } else {
            cmulp(re[slot], im[slot], per, pei, q);
            if (k + 2 < 16) cmulp(per, pei, w2r, w2i, q);
        }
    }
}

#define S1R 129   // pair-row stride (8B units); 129 mod 16 = 1 -> conflict-free
#define S2R 9     // 9 coprime 16 -> conflict-free
#define D4096 1.5339807878856412e-3f   // 2*pi/4096
#define D256  2.4543692606170259e-2f   // 2*pi/256
#define INV_N (1.0f / 4096.0f)

__global__ void __launch_bounds__(128) afdf_fft3_kernel(
    const float4* __restrict__ x4,
    const float4* __restrict__ A4,
    const float2* __restrict__ D2,
    float2* __restrict__ out2)
{
    // shared scratch, reused: S1 = 16 rows x 129 pairs; S2 = 256 rows x 9 pairs
    __shared__ ull sbuf[2 * 256 * S2R];          // 4608 ull = 36,864 B
    ull* const s1re = sbuf;  ull* const s1im = sbuf + 16 * S1R;   // 2064
    ull* const s2re = sbuf;  ull* const s2im = sbuf + 256 * S2R;  // 2304

    const PK q{ G_PKC[0], G_PKC[1], G_PKC[2] };   // opaque packed constants

    const int t  = threadIdx.x;        // 0..127
    const int c1 = t & 15;
    const int u  = t >> 4;             // 0..7
    const size_t rb4 = (size_t)blockIdx.x * 2048;   // row base in float4 units
    const size_t rb2 = (size_t)blockIdx.x * 4096;   // row base in float2 units

    ull re[16], im[16];

    // ---- load x, apply A; lanes = points m=(2t, 2t+1) ----
    #pragma unroll
    for (int a = 0; a < 16; ++a){
        const float4 xv = x4[rb4 + 128 * a + t];
        const float4 av = A4[128 * a + t];
        re[a] = pmul(pk(xv.x, xv.z), pk(av.x, av.z), q);
        im[a] = pmul(pk(xv.y, xv.w), pk(av.y, av.w), q);
    }

    // ================= forward =================
    fft16_nat_p<-1>(re, im, q);
    twiddle_stage_p<-1, 1>(re, im, (float)(2*t) * D4096, (float)(2*t + 1) * D4096, q);
    #pragma unroll
    for (int c = 0; c < 16; ++c){
        s1re[c * S1R + t] = re[REV(c)];
        s1im[c * S1R + t] = im[REV(c)];
    }
    __syncthreads();
    // stage 2: lanes = (b2 = 2u, 2u+1), iterate a2 (m = 16*a2 + b2)
    #pragma unroll
    for (int a2 = 0; a2 < 16; ++a2){
        re[a2] = s1re[c1 * S1R + 8 * a2 + u];
        im[a2] = s1im[c1 * S1R + 8 * a2 + u];
    }
    fft16_nat_p<-1>(re, im, q);
    twiddle_stage_p<-1, 1>(re, im, (float)(2*u) * D256, (float)(2*u + 1) * D256, q);
    __syncthreads();
    #pragma unroll
    for (int c2 = 0; c2 < 16; ++c2){
        const int r = 16 * c2 + c1;
        s2re[r * S2R + u] = re[REV(c2)];
        s2im[r * S2R + u] = im[REV(c2)];
    }
    __syncthreads();
    // stage 3: lanes = (r = t, t+128); stored pairs are along b2 -> repack
    #pragma unroll
    for (int uu = 0; uu < 8; ++uu){
        const ull Lr = s2re[t * S2R + uu],         Li = s2im[t * S2R + uu];
        const ull Hr = s2re[(t + 128) * S2R + uu], Hi = s2im[(t + 128) * S2R + uu];
        re[2*uu]     = pklo(Lr, Hr);  im[2*uu]     = pklo(Li, Hi);
        re[2*uu + 1] = pkhi(Lr, Hr);  im[2*uu + 1] = pkhi(Li, Hi);
    }
    fft16_nat_p<-1>(re, im, q);     // over b2; F[256*d2 + r] at slot REV(d2)

    // ---- D scale (1/N folded), freq = 256*d2 + (t | t+128) ----
    const ull invn2 = pk(INV_N, INV_N);
    #pragma unroll
    for (int d2 = 0; d2 < 16; ++d2){
        const float2 da = D2[256 * d2 + t];
        const float2 db = D2[256 * d2 + t + 128];
        const int s = REV(d2);
        re[s] = pmul(re[s], pmul(pk(da.x, db.x), invn2, q), q);
        im[s] = pmul(im[s], pmul(pk(da.y, db.y), invn2, q), q);
    }
    __syncthreads();

    // ================= inverse =================
    fft16_rev_p<1>(re, im, q);      // logical d2 at REV slot -> natural out
    twiddle_stage_p<1, 0>(re, im, (float)t * D4096, (float)(t + 128) * D4096, q);
    #pragma unroll
    for (int c = 0; c < 16; ++c){
        s1re[c * S1R + t] = re[c];   // pair = (r=t, r=t+128) at column t
        s1im[c * S1R + t] = im[c];
    }
    __syncthreads();
    // stage 2 inv: lanes = (b2 = u, u+8); stored pairs along a2 -> repack
    #pragma unroll
    for (int aa = 0; aa < 8; ++aa){
        const ull Lr = s1re[c1 * S1R + 16 * aa + u],     Li = s1im[c1 * S1R + 16 * aa + u];
        const ull Hr = s1re[c1 * S1R + 16 * aa + u + 8], Hi = s1im[c1 * S1R + 16 * aa + u + 8];
        re[aa]     = pklo(Lr, Hr);  im[aa]     = pklo(Li, Hi);
        re[aa + 8] = pkhi(Lr, Hr);  im[aa + 8] = pkhi(Li, Hi);
    }
    fft16_nat_p<1>(re, im, q);
    twiddle_stage_p<1, 1>(re, im, (float)u * D256, (float)(u + 8) * D256, q);
    __syncthreads();
    #pragma unroll
    for (int c2 = 0; c2 < 16; ++c2){
        const int r2 = 16 * c2 + c1;
        s2re[r2 * S2R + u] = re[REV(c2)];   // pair = (b2=u, u+8) at column u
        s2im[r2 * S2R + u] = im[REV(c2)];
    }
    __syncthreads();
    // stage 3 inv: lanes = (m = t, t+128); stored pairs along b2 -> repack
    #pragma unroll
    for (int uu = 0; uu < 8; ++uu){
        const ull Lr = s2re[t * S2R + uu],         Li = s2im[t * S2R + uu];
        const ull Hr = s2re[(t + 128) * S2R + uu], Hi = s2im[(t + 128) * S2R + uu];
        re[uu]     = pklo(Lr, Hr);  im[uu]     = pklo(Li, Hi);
        re[uu + 8] = pkhi(Lr, Hr);  im[uu + 8] = pkhi(Li, Hi);
    }
    fft16_nat_p<1>(re, im, q);      // over b2; out[256*d2 + m] at slot REV(d2)

    // ---- store ----
    #pragma unroll
    for (int d2 = 0; d2 < 16; ++d2){
        const int s = REV(d2);
        float r0, r1, i0, i1;
        unpk(re[s], r0, r1);
        unpk(im[s], i0, i1);
        out2[rb2 + 256 * d2 + t]       = make_float2(r0, i0);
        out2[rb2 + 256 * d2 + t + 128] = make_float2(r1, i1);
    }
}

extern "C" void kernel_launch(void* const* d_in, const int* in_sizes, int n_in,
                              void* d_out, int out_size)
{
    const float4* x4 = (const float4*)d_in[0];
    const float4* A4 = (const float4*)d_in[1];
    const float2* D2 = (const float2*)d_in[2];
    float2* out2 = (float2*)d_out;

    const int rows = in_sizes[0] / (4096 * 2);
    afdf_fft3_kernel<<<rows, 128>>>(x4, A4, D2, out2);
}